// round 12
// baseline (speedup 1.0000x reference)
#include <cuda_runtime.h>

#define B_ 8
#define T_ 200
#define U_ 50
#define V_ 1024
#define NC_ (2 * U_ - 1)
#define NEG_INF (-1e30f)
#define LOG2E_F 1.4426950408889634f
#define LN2_F   0.6931471805599453f
#define NS_ 62            /* max macro (radix-4) steps */
#define P4S 250           /* 5 * 50 floats per macro step */
#define ASL 52            /* A slab row: 50 u + 2 guard */
#define ASS (3 * ASL)

__device__ float g_scratch[B_ * NC_ * T_];   // log2-domain: bl[u][t] then em[u][t]
__device__ float g_partial[B_];
__device__ int   g_count = 0;
__device__ int   g_colcnt[B_];               // zero-init; reset each run by DP blocks

__device__ __forceinline__ float ex2f(float x) {
    float y; asm("ex2.approx.f32 %0, %1;" : "=f"(y) : "f"(x)); return y;
}
__device__ __forceinline__ float lg2f(float x) {
    float y; asm("lg2.approx.f32 %0, %1;" : "=f"(y) : "f"(x)); return y;
}
__device__ __forceinline__ float lse2(float x, float y) {
    float m = fmaxf(x, y);
    return m + lg2f(ex2f(x - m) + ex2f(y - m));
}
__device__ __forceinline__ float lse3(float x, float y, float z) {
    float m = fmaxf(fmaxf(x, y), z);
    return m + lg2f(ex2f(x - m) + ex2f(y - m) + ex2f(z - m));
}
__device__ __forceinline__ float getbl(const float* bl, int d, int u) {
    int t = d - u;
    return (u >= 0 && u < U_ && t >= 0 && t <= T_ - 2) ? bl[u * T_ + t] : NEG_INF;
}
__device__ __forceinline__ float getem(const float* em, int d, int u) {
    int t = d + 1 - u;
    return (u >= 1 && u < U_ && t >= 0 && t <= T_ - 1) ? em[(u - 1) * T_ + t] : NEG_INF;
}

// smem layout for DP-role blocks
#define SP_PAD 64
#define SP_FLOATS (NS_ * P4S + SP_PAD)
#define SA_FLOATS (NS_ * ASS)
#define SMEM_FLOATS (SP_FLOATS + SA_FLOATS + U_ * T_ + (U_ - 1) * T_)
#define SMEM_BYTES  (SMEM_FLOATS * 4)

extern "C" __global__ void __launch_bounds__(256, 1)
rnnt_fused(const float* __restrict__ h,
           const int* __restrict__ targets,
           const int* __restrict__ input_lens,
           const int* __restrict__ target_lens,
           float* __restrict__ out)
{
    extern __shared__ float smem[];
    const int bid = blockIdx.x;
    const int tid = threadIdx.x;

    // ===================== phase1 column role (bids 8..799) =================
    if (bid >= B_) {
        const int cl = bid - B_;
        const int b  = cl / NC_;
        const int c  = cl - b * NC_;

        int u, v;
        if (c < U_) { u = c;       v = 0; }
        else        { u = c - U_;  v = targets[b * (U_ - 1) + u]; }

        const float* col = h + ((long long)b * T_ * U_ + u) * V_ + v;

        const int t = tid;
        float w = (t < T_) ? col[(long long)t * (U_ * V_)] * LOG2E_F : NEG_INF;

        __shared__ float red[16];
        const int lane = t & 31, wid = t >> 5;

        float m = w;
        #pragma unroll
        for (int o = 16; o; o >>= 1) m = fmaxf(m, __shfl_xor_sync(0xffffffffu, m, o));
        if (lane == 0) red[wid] = m;
        __syncthreads();
        m = red[0];
        #pragma unroll
        for (int i = 1; i < 8; i++) m = fmaxf(m, red[i]);

        float e = (t < T_) ? ex2f(w - m) : 0.0f;
        #pragma unroll
        for (int o = 16; o; o >>= 1) e += __shfl_xor_sync(0xffffffffu, e, o);
        if (lane == 0) red[8 + wid] = e;
        __syncthreads();
        float s = red[8];
        #pragma unroll
        for (int i = 1; i < 8; i++) s += red[8 + i];

        float L = m + lg2f(s);
        if (t < T_) g_scratch[(b * NC_ + c) * T_ + t] = w - L;

        __syncthreads();                 // all stores issued block-wide
        if (tid == 0) {
            __threadfence();             // release scratch to GPU scope
            atomicAdd(&g_colcnt[b], 1);
        }
        return;
    }

    // ===================== DP role (bids 0..7) ==============================
    const int b = bid;
    float* sP  = smem;                        // [NS_][5][50] + pad
    float* sA  = smem + SP_FLOATS;            // [NS_][3][52]
    float* sbl = sA + SA_FLOATS;              // [50][200]
    float* sem = sbl + U_ * T_;               // [49][200]
    __shared__ float s_al[144];               // alpha exchange, 2 x 72

    // wait until this batch's 99 columns are published
    if (tid == 0) {
        int v;
        do {
            asm volatile("ld.acquire.gpu.global.b32 %0, [%1];"
                         : "=r"(v) : "l"(&g_colcnt[b]) : "memory");
            if (v < NC_) __nanosleep(64);
        } while (v < NC_);
        g_colcnt[b] = 0;                 // reset for next graph replay
    }
    __syncthreads();

    { // stage bl/em + guards
        const float4* srcS = (const float4*)(g_scratch + b * (NC_ * T_));
        float4* dstS = (float4*)sbl;
        #pragma unroll 4
        for (int i = tid; i < NC_ * T_ / 4; i += 256) dstS[i] = srcS[i];
        if (tid < SP_PAD) sP[NS_ * P4S + tid] = NEG_INF;
        for (int i = tid; i < NS_ * 3 * 2; i += 256) {
            int sm = i >> 1;
            sA[sm * ASL + (i & 1)] = NEG_INF;
        }
        if (tid < 6) { s_al[tid] = NEG_INF; s_al[72 + tid] = NEG_INF; }
    }
    __syncthreads();

    // compose pass A: A = M_{d0+1} o M_{d0}
    for (int i = tid; i < NS_ * U_; i += 256) {
        int s = i / U_;
        int u = i - s * U_;
        int d0 = 4 * s;
        float M0_0  = getbl(sbl, d0, u),     M0_1  = getem(sem, d0, u);
        float M0_0m = getbl(sbl, d0, u - 1), M0_1m = getem(sem, d0, u - 1);
        float M1_0  = getbl(sbl, d0 + 1, u), M1_1  = getem(sem, d0 + 1, u);
        float* a = sA + s * ASS;
        a[0 * ASL + u + 2] = M1_0 + M0_0;
        a[1 * ASL + u + 2] = lse2(M1_0 + M0_1, M1_1 + M0_0m);
        a[2 * ASL + u + 2] = M1_1 + M0_1m;
    }
    __syncthreads();

    // compose pass P: B = M_{d0+3} o M_{d0+2};  P = B o A
    for (int i = tid; i < NS_ * U_; i += 256) {
        int s = i / U_;
        int u = i - s * U_;
        int d0 = 4 * s;
        float M2_0  = getbl(sbl, d0 + 2, u),     M2_1  = getem(sem, d0 + 2, u);
        float M2_0m = getbl(sbl, d0 + 2, u - 1), M2_1m = getem(sem, d0 + 2, u - 1);
        float M3_0  = getbl(sbl, d0 + 3, u),     M3_1  = getem(sem, d0 + 3, u);
        float B0 = M3_0 + M2_0;
        float B1 = lse2(M3_0 + M2_1, M3_1 + M2_0m);
        float B2 = M3_1 + M2_1m;

        const float* a = sA + s * ASS;
        float A0    = a[0 * ASL + u + 2], A1    = a[1 * ASL + u + 2], A2    = a[2 * ASL + u + 2];
        float Am1_0 = a[0 * ASL + u + 1], Am1_1 = a[1 * ASL + u + 1], Am1_2 = a[2 * ASL + u + 1];
        float Am2_0 = a[0 * ASL + u    ], Am2_1 = a[1 * ASL + u    ], Am2_2 = a[2 * ASL + u    ];

        float* o = sP + s * P4S;
        o[0 * U_ + u] = B0 + A0;
        o[1 * U_ + u] = lse2(B0 + A1, B1 + Am1_0);
        o[2 * U_ + u] = lse3(B0 + A2, B1 + Am1_1, B2 + Am2_0);
        o[3 * U_ + u] = lse2(B1 + Am1_2, B2 + Am2_1);
        o[4 * U_ + u] = B2 + Am2_2;
    }
    __syncthreads();

    if (tid >= 32) return;
    const int lane = tid;
    const int ti   = input_lens[b]  - 1;
    const int ui   = target_lens[b] - 1;
    const int dcap = ti + ui;
    const int S    = dcap >> 2;
    const int rem  = dcap & 3;

    float ap0 = (lane == 0) ? 0.0f : NEG_INF;   // u = lane
    float ap1 = NEG_INF;                        // u = lane + 32

    const float* pw = sP;
    int base = 0;
    for (int s = 0; s < S; s++) {
        float p00 = pw[          lane], p01 = pw[1 * U_ +  lane];
        float p02 = pw[2 * U_ +  lane], p03 = pw[3 * U_ +  lane];
        float p04 = pw[4 * U_ +  lane];
        float p10 = pw[     32 + lane], p11 = pw[1 * U_ + 32 + lane];
        float p12 = pw[2 * U_ + 32 + lane], p13 = pw[3 * U_ + 32 + lane];
        float p14 = pw[4 * U_ + 32 + lane];

        s_al[base + 6  + lane] = ap0;
        s_al[base + 38 + lane] = ap1;
        __syncwarp();
        float a0m1 = s_al[base + 5  + lane];
        float a0m2 = s_al[base + 4  + lane];
        float a0m3 = s_al[base + 3  + lane];
        float a0m4 = s_al[base + 2  + lane];
        float a1m1 = s_al[base + 37 + lane];
        float a1m2 = s_al[base + 36 + lane];
        float a1m3 = s_al[base + 35 + lane];
        float a1m4 = s_al[base + 34 + lane];
        base ^= 72;

        float v00 = ap0  + p00;
        float v01 = a0m1 + p01;
        float v02 = a0m2 + p02;
        float v03 = a0m3 + p03;
        float v04 = a0m4 + p04;
        float v10 = ap1  + p10;
        float v11 = a1m1 + p11;
        float v12 = a1m2 + p12;
        float v13 = a1m3 + p13;
        float v14 = a1m4 + p14;

        float m0 = fmaxf(fmaxf(fmaxf(v00, v01), fmaxf(v02, v03)), v04);
        float m1 = fmaxf(fmaxf(fmaxf(v10, v11), fmaxf(v12, v13)), v14);
        float s0 = ex2f(v00 - m0) + ex2f(v01 - m0) + ex2f(v02 - m0)
                 + ex2f(v03 - m0) + ex2f(v04 - m0);
        float s1 = ex2f(v10 - m1) + ex2f(v11 - m1) + ex2f(v12 - m1)
                 + ex2f(v13 - m1) + ex2f(v14 - m1);
        ap0 = m0 + lg2f(s0);
        ap1 = m1 + lg2f(s1);
        pw += P4S;
    }

    // remainder single steps (<= 3)
    int D = 4 * S;
    for (int r = 0; r < rem; r++, D++) {
        float l0  = __shfl_up_sync(0xffffffffu, ap0, 1);
        float a31 = __shfl_sync   (0xffffffffu, ap0, 31);
        float l1  = __shfl_up_sync(0xffffffffu, ap1, 1);
        if (lane == 0) { l0 = NEG_INF; l1 = a31; }

        int u = lane;
        int tb = D - u, te = D + 1 - u;
        float bl0 = (tb >= 0 && tb <= T_ - 2) ? sbl[u * T_ + tb] : NEG_INF;
        float em0 = (u >= 1 && te >= 0 && te < T_) ? sem[(u - 1) * T_ + te] : NEG_INF;
        float x0 = ap0 + bl0, y0 = l0 + em0;
        float mm0 = fmaxf(x0, y0);
        ap0 = mm0 + lg2f(ex2f(x0 - mm0) + ex2f(y0 - mm0));

        u = lane + 32;
        tb = D - u; te = D + 1 - u;
        float bl1 = (u < U_ && tb >= 0 && tb <= T_ - 2) ? sbl[u * T_ + tb] : NEG_INF;
        float em1 = (u < U_ && te >= 0 && te < T_) ? sem[(u - 1) * T_ + te] : NEG_INF;
        float x1 = ap1 + bl1, y1 = l1 + em1;
        float mm1 = fmaxf(x1, y1);
        ap1 = mm1 + lg2f(ex2f(x1 - mm1) + ex2f(y1 - mm1));
    }

    const bool own0 = (lane == ui);
    const bool own1 = (lane + 32 == ui);
    if (own0 | own1) {
        float a   = own0 ? ap0 : ap1;
        float fin = (a + sbl[ui * T_ + ti]) * LN2_F;
        g_partial[b] = fin;
        __threadfence();
        if (atomicAdd(&g_count, 1) == B_ - 1) {
            __threadfence();
            float sum = 0.0f;
            #pragma unroll
            for (int i = 0; i < B_; i++) sum += *((volatile float*)&g_partial[i]);
            out[0] = -sum * (1.0f / (float)B_);
            g_count = 0;   // reset for next graph replay
        }
    }
}

extern "C" void kernel_launch(void* const* d_in, const int* in_sizes, int n_in,
                              void* d_out, int out_size)
{
    (void)in_sizes; (void)n_in; (void)out_size;
    const float* h           = (const float*)d_in[0];
    const int*   targets     = (const int*)d_in[1];
    const int*   input_lens  = (const int*)d_in[2];
    const int*   target_lens = (const int*)d_in[3];

    cudaFuncSetAttribute(rnnt_fused, cudaFuncAttributeMaxDynamicSharedMemorySize, SMEM_BYTES);

    rnnt_fused<<<B_ + B_ * NC_, 256, SMEM_BYTES>>>(h, targets, input_lens, target_lens,
                                                   (float*)d_out);
}

// round 14
// speedup vs baseline: 1.2764x; 1.2764x over previous
#include <cuda_runtime.h>

#define B_ 8
#define T_ 200
#define U_ 50
#define V_ 1024
#define NC_ (2 * U_ - 1)
#define NEG_INF (-1e30f)
#define LOG2E_F 1.4426950408889634f
#define LN2_F   0.6931471805599453f
#define NS_ 62            /* max macro (radix-4) steps */
#define P4S 250           /* 5 * 50 floats per macro step */

__device__ float g_gather[B_ * T_ * NC_];    // compact [b][t][c] raw h values
__device__ float g_scratch[B_ * NC_ * T_];   // log2-domain: bl[u][t] then em[u][t]
__device__ float g_p4[B_ * NS_ * P4S];       // composed ops [b][s][k][u]
__device__ float g_partial[B_];
__device__ int   g_count = 0;

__device__ __forceinline__ float ex2f(float x) {
    float y; asm("ex2.approx.f32 %0, %1;" : "=f"(y) : "f"(x)); return y;
}
__device__ __forceinline__ float lg2f(float x) {
    float y; asm("lg2.approx.f32 %0, %1;" : "=f"(y) : "f"(x)); return y;
}
__device__ __forceinline__ float lse2(float x, float y) {
    float m = fmaxf(x, y);
    return m + lg2f(ex2f(x - m) + ex2f(y - m));
}
__device__ __forceinline__ float lse3(float x, float y, float z) {
    float m = fmaxf(fmaxf(x, y), z);
    return m + lg2f(ex2f(x - m) + ex2f(y - m) + ex2f(z - m));
}
__device__ __forceinline__ float getbl(const float* bl, int d, int u) {
    int t = d - u;
    return (u >= 0 && u < U_ && t >= 0 && t <= T_ - 2) ? bl[u * T_ + t] : NEG_INF;
}
__device__ __forceinline__ float getem(const float* em, int d, int u) {
    int t = d + 1 - u;
    return (u >= 1 && u < U_ && t >= 0 && t <= T_ - 1) ? em[(u - 1) * T_ + t] : NEG_INF;
}

// ---- Phase 0: (b,t)-local gather. 1600 blocks x 128 thr. ----
// Each block reads 99 scattered floats from ONE 200KB window (row/TLB-local),
// writes them coalesced to g_gather[b][t][c].
extern "C" __global__ void __launch_bounds__(128, 8)
rnnt_gather(const float* __restrict__ h, const int* __restrict__ targets)
{
    const int bid = blockIdx.x;
    const int b   = bid / T_;
    const int t   = bid - b * T_;
    const int c   = threadIdx.x;
    if (c >= NC_) return;

    int u, v;
    if (c < U_) { u = c;       v = 0; }
    else        { u = c - U_;  v = targets[b * (U_ - 1) + (c - U_)]; }

    float val = h[((long long)b * T_ + t) * (U_ * V_) + u * V_ + v];
    g_gather[(b * T_ + t) * NC_ + c] = val;
}

// ---- Phase 1: per-column softmax over T, reading compact L2-resident data --
extern "C" __global__ void __launch_bounds__(256, 8)
rnnt_softmax(void)
{
    const int bid = blockIdx.x;
    const int b   = bid / NC_;
    const int c   = bid - b * NC_;

    const float* col = g_gather + (long long)b * T_ * NC_ + c;

    const int t = threadIdx.x;
    float w = (t < T_) ? col[t * NC_] * LOG2E_F : NEG_INF;

    __shared__ float red[16];
    const int lane = t & 31, wid = t >> 5;

    float m = w;
    #pragma unroll
    for (int o = 16; o; o >>= 1) m = fmaxf(m, __shfl_xor_sync(0xffffffffu, m, o));
    if (lane == 0) red[wid] = m;
    __syncthreads();
    m = red[0];
    #pragma unroll
    for (int i = 1; i < 8; i++) m = fmaxf(m, red[i]);

    float e = (t < T_) ? ex2f(w - m) : 0.0f;
    #pragma unroll
    for (int o = 16; o; o >>= 1) e += __shfl_xor_sync(0xffffffffu, e, o);
    if (lane == 0) red[8 + wid] = e;
    __syncthreads();
    float s = red[8];
    #pragma unroll
    for (int i = 1; i < 8; i++) s += red[8 + i];

    float L = m + lg2f(s);
    if (t < T_) g_scratch[bid * T_ + t] = w - L;
}

// ---------------- Phase 1.5: compose 4 diagonals into band-4 ops ------------
extern "C" __global__ void __launch_bounds__(64, 16)
rnnt_compose(void)
{
    const int b = blockIdx.x / NS_;
    const int s = blockIdx.x - b * NS_;
    const int u = threadIdx.x;
    const int d0 = 4 * s;

    const float* bl = g_scratch + b * NC_ * T_;
    const float* em = bl + U_ * T_;

    __shared__ float sA[(64 + 2) * 3];
    if (u < 2) { sA[u * 3 + 0] = NEG_INF; sA[u * 3 + 1] = NEG_INF; sA[u * 3 + 2] = NEG_INF; }

    float M0_0  = getbl(bl, d0, u),     M0_1  = getem(em, d0, u);
    float M0_0m = getbl(bl, d0, u - 1), M0_1m = getem(em, d0, u - 1);
    float M1_0  = getbl(bl, d0 + 1, u), M1_1  = getem(em, d0 + 1, u);
    float A0 = M1_0 + M0_0;
    float A1 = lse2(M1_0 + M0_1, M1_1 + M0_0m);
    float A2 = M1_1 + M0_1m;

    float M2_0  = getbl(bl, d0 + 2, u),     M2_1  = getem(em, d0 + 2, u);
    float M2_0m = getbl(bl, d0 + 2, u - 1), M2_1m = getem(em, d0 + 2, u - 1);
    float M3_0  = getbl(bl, d0 + 3, u),     M3_1  = getem(em, d0 + 3, u);
    float B0 = M3_0 + M2_0;
    float B1 = lse2(M3_0 + M2_1, M3_1 + M2_0m);
    float B2 = M3_1 + M2_1m;

    sA[(u + 2) * 3 + 0] = A0;
    sA[(u + 2) * 3 + 1] = A1;
    sA[(u + 2) * 3 + 2] = A2;
    __syncthreads();

    float Am1_0 = sA[(u + 1) * 3 + 0], Am1_1 = sA[(u + 1) * 3 + 1], Am1_2 = sA[(u + 1) * 3 + 2];
    float Am2_0 = sA[(u    ) * 3 + 0], Am2_1 = sA[(u    ) * 3 + 1], Am2_2 = sA[(u    ) * 3 + 2];

    float P0 = B0 + A0;
    float P1 = lse2(B0 + A1, B1 + Am1_0);
    float P2 = lse3(B0 + A2, B1 + Am1_1, B2 + Am2_0);
    float P3 = lse2(B1 + Am1_2, B2 + Am2_1);
    float P4v = B2 + Am2_2;

    if (u < U_) {
        float* o = g_p4 + (b * NS_ + s) * P4S;
        o[0 * U_ + u] = P0;
        o[1 * U_ + u] = P1;
        o[2 * U_ + u] = P2;
        o[3 * U_ + u] = P3;
        o[4 * U_ + u] = P4v;
    }
}

// ------ Phase 2: radix-4 DP, smem double-buffered alpha exchange ------------
#define SP_PAD 64
#define SP_FLOATS (NS_ * P4S + SP_PAD)
#define SMEM_FLOATS (SP_FLOATS + U_ * T_ + (U_ - 1) * T_)
#define SMEM_BYTES  (SMEM_FLOATS * 4)

extern "C" __global__ void __launch_bounds__(512, 1)
rnnt_phase2(const int* __restrict__ input_lens,
            const int* __restrict__ target_lens,
            float* __restrict__ out)
{
    extern __shared__ float smem[];
    float* sP  = smem;                 // [NS_][5][50] + pad
    float* sbl = smem + SP_FLOATS;     // [50][200]
    float* sem = sbl + U_ * T_;        // [49][200]
    __shared__ float s_al[144];        // alpha exchange, 2 x 72

    const int b = blockIdx.x, tid = threadIdx.x;

    {
        const float4* srcP = (const float4*)(g_p4 + b * (NS_ * P4S));
        float4* dstP = (float4*)sP;
        #pragma unroll 4
        for (int i = tid; i < NS_ * P4S / 4; i += 512) dstP[i] = srcP[i];
        if (tid < SP_PAD) sP[NS_ * P4S + tid] = NEG_INF;
        const float4* srcS = (const float4*)(g_scratch + b * (NC_ * T_));
        float4* dstS = (float4*)sbl;
        #pragma unroll 4
        for (int i = tid; i < NC_ * T_ / 4; i += 512) dstS[i] = srcS[i];
        if (tid < 6) { s_al[tid] = NEG_INF; s_al[72 + tid] = NEG_INF; }
    }
    __syncthreads();
    if (tid >= 32) return;

    const int lane = tid;
    const int ti   = input_lens[b]  - 1;
    const int ui   = target_lens[b] - 1;
    const int dcap = ti + ui;
    const int S    = dcap >> 2;
    const int rem  = dcap & 3;

    float ap0 = (lane == 0) ? 0.0f : NEG_INF;   // u = lane
    float ap1 = NEG_INF;                        // u = lane + 32

    const float* pw = sP;
    int base = 0;
    for (int s = 0; s < S; s++) {
        float p00 = pw[          lane], p01 = pw[1 * U_ +  lane];
        float p02 = pw[2 * U_ +  lane], p03 = pw[3 * U_ +  lane];
        float p04 = pw[4 * U_ +  lane];
        float p10 = pw[     32 + lane], p11 = pw[1 * U_ + 32 + lane];
        float p12 = pw[2 * U_ + 32 + lane], p13 = pw[3 * U_ + 32 + lane];
        float p14 = pw[4 * U_ + 32 + lane];

        s_al[base + 6  + lane] = ap0;
        s_al[base + 38 + lane] = ap1;
        __syncwarp();
        float a0m1 = s_al[base + 5  + lane];
        float a0m2 = s_al[base + 4  + lane];
        float a0m3 = s_al[base + 3  + lane];
        float a0m4 = s_al[base + 2  + lane];
        float a1m1 = s_al[base + 37 + lane];
        float a1m2 = s_al[base + 36 + lane];
        float a1m3 = s_al[base + 35 + lane];
        float a1m4 = s_al[base + 34 + lane];
        base ^= 72;

        float v00 = ap0  + p00;
        float v01 = a0m1 + p01;
        float v02 = a0m2 + p02;
        float v03 = a0m3 + p03;
        float v04 = a0m4 + p04;
        float v10 = ap1  + p10;
        float v11 = a1m1 + p11;
        float v12 = a1m2 + p12;
        float v13 = a1m3 + p13;
        float v14 = a1m4 + p14;

        float m0 = fmaxf(fmaxf(fmaxf(v00, v01), fmaxf(v02, v03)), v04);
        float m1 = fmaxf(fmaxf(fmaxf(v10, v11), fmaxf(v12, v13)), v14);
        float s0 = ex2f(v00 - m0) + ex2f(v01 - m0) + ex2f(v02 - m0)
                 + ex2f(v03 - m0) + ex2f(v04 - m0);
        float s1 = ex2f(v10 - m1) + ex2f(v11 - m1) + ex2f(v12 - m1)
                 + ex2f(v13 - m1) + ex2f(v14 - m1);
        ap0 = m0 + lg2f(s0);
        ap1 = m1 + lg2f(s1);
        pw += P4S;
    }

    // remainder single steps (<= 3)
    int D = 4 * S;
    for (int r = 0; r < rem; r++, D++) {
        float l0  = __shfl_up_sync(0xffffffffu, ap0, 1);
        float a31 = __shfl_sync   (0xffffffffu, ap0, 31);
        float l1  = __shfl_up_sync(0xffffffffu, ap1, 1);
        if (lane == 0) { l0 = NEG_INF; l1 = a31; }

        int u = lane;
        int tb = D - u, te = D + 1 - u;
        float bl0 = (tb >= 0 && tb <= T_ - 2) ? sbl[u * T_ + tb] : NEG_INF;
        float em0 = (u >= 1 && te >= 0 && te < T_) ? sem[(u - 1) * T_ + te] : NEG_INF;
        float x0 = ap0 + bl0, y0 = l0 + em0;
        float mm0 = fmaxf(x0, y0);
        ap0 = mm0 + lg2f(ex2f(x0 - mm0) + ex2f(y0 - mm0));

        u = lane + 32;
        tb = D - u; te = D + 1 - u;
        float bl1 = (u < U_ && tb >= 0 && tb <= T_ - 2) ? sbl[u * T_ + tb] : NEG_INF;
        float em1 = (u < U_ && te >= 0 && te < T_) ? sem[(u - 1) * T_ + te] : NEG_INF;
        float x1 = ap1 + bl1, y1 = l1 + em1;
        float mm1 = fmaxf(x1, y1);
        ap1 = mm1 + lg2f(ex2f(x1 - mm1) + ex2f(y1 - mm1));
    }

    const bool own0 = (lane == ui);
    const bool own1 = (lane + 32 == ui);
    if (own0 | own1) {
        float a   = own0 ? ap0 : ap1;
        float fin = (a + sbl[ui * T_ + ti]) * LN2_F;
        g_partial[b] = fin;
        __threadfence();
        if (atomicAdd(&g_count, 1) == B_ - 1) {
            __threadfence();
            float sum = 0.0f;
            #pragma unroll
            for (int i = 0; i < B_; i++) sum += *((volatile float*)&g_partial[i]);
            out[0] = -sum * (1.0f / (float)B_);
            g_count = 0;   // reset for next graph replay
        }
    }
}

extern "C" void kernel_launch(void* const* d_in, const int* in_sizes, int n_in,
                              void* d_out, int out_size)
{
    (void)in_sizes; (void)n_in; (void)out_size;
    const float* h           = (const float*)d_in[0];
    const int*   targets     = (const int*)d_in[1];
    const int*   input_lens  = (const int*)d_in[2];
    const int*   target_lens = (const int*)d_in[3];

    cudaFuncSetAttribute(rnnt_phase2, cudaFuncAttributeMaxDynamicSharedMemorySize, SMEM_BYTES);

    rnnt_gather<<<B_ * T_, 128>>>(h, targets);
    rnnt_softmax<<<B_ * NC_, 256>>>();
    rnnt_compose<<<B_ * NS_, 64>>>();
    rnnt_phase2<<<B_, 512, SMEM_BYTES>>>(input_lens, target_lens, (float*)d_out);
}

// round 16
// speedup vs baseline: 1.4009x; 1.0976x over previous
#include <cuda_runtime.h>

#define B_ 8
#define T_ 200
#define U_ 50
#define V_ 1024
#define NC_ (2 * U_ - 1)
#define NEG_INF (-1e30f)
#define LOG2E_F 1.4426950408889634f
#define LN2_F   0.6931471805599453f
#define NS_ 62            /* max macro (radix-4) steps */
#define P4S 250           /* 5 * 50 floats per macro step */

__device__ float g_scratch[B_ * NC_ * T_];   // log2-domain: bl[u][t] then em[u][t]
__device__ float g_p4[B_ * NS_ * P4S];       // LINEAR composed ops exp2(P - c_s)
__device__ float g_c[B_ * NS_];              // per-step scale c_s (log2)
__device__ float g_partial[B_];
__device__ int   g_count = 0;

__device__ __forceinline__ float ex2f(float x) {
    float y; asm("ex2.approx.f32 %0, %1;" : "=f"(y) : "f"(x)); return y;
}
__device__ __forceinline__ float lg2f(float x) {
    float y; asm("lg2.approx.f32 %0, %1;" : "=f"(y) : "f"(x)); return y;
}
__device__ __forceinline__ float lse2(float x, float y) {
    float m = fmaxf(x, y);
    return m + lg2f(ex2f(x - m) + ex2f(y - m));
}
__device__ __forceinline__ float lse3(float x, float y, float z) {
    float m = fmaxf(fmaxf(x, y), z);
    return m + lg2f(ex2f(x - m) + ex2f(y - m) + ex2f(z - m));
}
__device__ __forceinline__ float getbl(const float* bl, int d, int u) {
    int t = d - u;
    return (u >= 0 && u < U_ && t >= 0 && t <= T_ - 2) ? bl[u * T_ + t] : NEG_INF;
}
__device__ __forceinline__ float getem(const float* em, int d, int u) {
    int t = d + 1 - u;
    return (u >= 1 && u < U_ && t >= 0 && t <= T_ - 1) ? em[(u - 1) * T_ + t] : NEG_INF;
}

// ------- Phase 1: one column per block (at the random-line DRAM floor) ------
extern "C" __global__ void __launch_bounds__(256, 8)
rnnt_phase1(const float* __restrict__ h, const int* __restrict__ targets)
{
    const int bid = blockIdx.x;
    const int b   = bid / NC_;
    const int c   = bid - b * NC_;

    int u, v;
    if (c < U_) { u = c;       v = 0; }
    else        { u = c - U_;  v = targets[b * (U_ - 1) + u]; }

    const float* col = h + ((long long)b * T_ * U_ + u) * V_ + v;

    const int t = threadIdx.x;
    float w = (t < T_) ? col[(long long)t * (U_ * V_)] * LOG2E_F : NEG_INF;

    __shared__ float red[16];
    const int lane = t & 31, wid = t >> 5;

    float m = w;
    #pragma unroll
    for (int o = 16; o; o >>= 1) m = fmaxf(m, __shfl_xor_sync(0xffffffffu, m, o));
    if (lane == 0) red[wid] = m;
    __syncthreads();
    m = red[0];
    #pragma unroll
    for (int i = 1; i < 8; i++) m = fmaxf(m, red[i]);

    float e = (t < T_) ? ex2f(w - m) : 0.0f;
    #pragma unroll
    for (int o = 16; o; o >>= 1) e += __shfl_xor_sync(0xffffffffu, e, o);
    if (lane == 0) red[8 + wid] = e;
    __syncthreads();
    float s = red[8];
    #pragma unroll
    for (int i = 1; i < 8; i++) s += red[8 + i];

    float L = m + lg2f(s);
    if (t < T_) g_scratch[bid * T_ + t] = w - L;
}

// ---- Phase 1.5: compose 4 diagonals -> band-4 op, scaled to linear ---------
extern "C" __global__ void __launch_bounds__(64, 16)
rnnt_compose(void)
{
    const int b = blockIdx.x / NS_;
    const int s = blockIdx.x - b * NS_;
    const int u = threadIdx.x;
    const int lane = u & 31, wid = u >> 5;
    const int d0 = 4 * s;

    const float* bl = g_scratch + b * NC_ * T_;
    const float* em = bl + U_ * T_;

    __shared__ float sA[(64 + 2) * 3];
    __shared__ float swm[2];
    if (u < 2) { sA[u * 3 + 0] = NEG_INF; sA[u * 3 + 1] = NEG_INF; sA[u * 3 + 2] = NEG_INF; }

    float M0_0  = getbl(bl, d0, u),     M0_1  = getem(em, d0, u);
    float M0_0m = getbl(bl, d0, u - 1), M0_1m = getem(em, d0, u - 1);
    float M1_0  = getbl(bl, d0 + 1, u), M1_1  = getem(em, d0 + 1, u);
    float A0 = M1_0 + M0_0;
    float A1 = lse2(M1_0 + M0_1, M1_1 + M0_0m);
    float A2 = M1_1 + M0_1m;

    float M2_0  = getbl(bl, d0 + 2, u),     M2_1  = getem(em, d0 + 2, u);
    float M2_0m = getbl(bl, d0 + 2, u - 1), M2_1m = getem(em, d0 + 2, u - 1);
    float M3_0  = getbl(bl, d0 + 3, u),     M3_1  = getem(em, d0 + 3, u);
    float B0 = M3_0 + M2_0;
    float B1 = lse2(M3_0 + M2_1, M3_1 + M2_0m);
    float B2 = M3_1 + M2_1m;

    sA[(u + 2) * 3 + 0] = A0;
    sA[(u + 2) * 3 + 1] = A1;
    sA[(u + 2) * 3 + 2] = A2;
    __syncthreads();

    float Am1_0 = sA[(u + 1) * 3 + 0], Am1_1 = sA[(u + 1) * 3 + 1], Am1_2 = sA[(u + 1) * 3 + 2];
    float Am2_0 = sA[(u    ) * 3 + 0], Am2_1 = sA[(u    ) * 3 + 1], Am2_2 = sA[(u    ) * 3 + 2];

    float P0 = B0 + A0;
    float P1 = lse2(B0 + A1, B1 + Am1_0);
    float P2 = lse3(B0 + A2, B1 + Am1_1, B2 + Am2_0);
    float P3 = lse2(B1 + Am1_2, B2 + Am2_1);
    float P4v = B2 + Am2_2;

    // block max c_s over all u and bands (invalid u give huge negatives: harmless)
    float cm = fmaxf(fmaxf(fmaxf(P0, P1), fmaxf(P2, P3)), P4v);
    #pragma unroll
    for (int o = 16; o; o >>= 1) cm = fmaxf(cm, __shfl_xor_sync(0xffffffffu, cm, o));
    if (lane == 0) swm[wid] = cm;
    __syncthreads();
    float c = fmaxf(swm[0], swm[1]);

    if (u < U_) {
        float* o = g_p4 + (b * NS_ + s) * P4S;
        o[0 * U_ + u] = ex2f(P0 - c);
        o[1 * U_ + u] = ex2f(P1 - c);
        o[2 * U_ + u] = ex2f(P2 - c);
        o[3 * U_ + u] = ex2f(P3 - c);
        o[4 * U_ + u] = ex2f(P4v - c);
    }
    if (u == 0) g_c[b * NS_ + s] = c;
}

// ------ Phase 2: LINEAR radix-4 DP (FMA only) + renorm + fused reduction ----
#define SP_PAD 64
#define SP_FLOATS (NS_ * P4S + SP_PAD)
#define SMEM_FLOATS (SP_FLOATS + U_ * T_ + (U_ - 1) * T_)
#define SMEM_BYTES  (SMEM_FLOATS * 4)

extern "C" __global__ void __launch_bounds__(512, 1)
rnnt_phase2(const int* __restrict__ input_lens,
            const int* __restrict__ target_lens,
            float* __restrict__ out)
{
    extern __shared__ float smem[];
    float* sP  = smem;                 // [NS_][5][50] + pad (LINEAR p, pad = 0)
    float* sbl = smem + SP_FLOATS;     // [50][200] (log2)
    float* sem = sbl + U_ * T_;        // [49][200] (log2)
    __shared__ float s_al[144];        // alpha exchange (linear), 2 x 72
    __shared__ float s_c[NS_];         // per-step scales

    const int b = blockIdx.x, tid = threadIdx.x;

    {
        const float4* srcP = (const float4*)(g_p4 + b * (NS_ * P4S));
        float4* dstP = (float4*)sP;
        #pragma unroll 4
        for (int i = tid; i < NS_ * P4S / 4; i += 512) dstP[i] = srcP[i];
        if (tid < SP_PAD) sP[NS_ * P4S + tid] = 0.0f;          // linear pad = 0
        const float4* srcS = (const float4*)(g_scratch + b * (NC_ * T_));
        float4* dstS = (float4*)sbl;
        #pragma unroll 4
        for (int i = tid; i < NC_ * T_ / 4; i += 512) dstS[i] = srcS[i];
        if (tid < 6) { s_al[tid] = 0.0f; s_al[72 + tid] = 0.0f; }  // linear guards
        if (tid < NS_) s_c[tid] = g_c[b * NS_ + tid];
    }
    __syncthreads();
    if (tid >= 32) return;

    const int lane = tid;
    const int ti   = input_lens[b]  - 1;
    const int ui   = target_lens[b] - 1;
    const int dcap = ti + ui;
    const int S    = dcap >> 2;
    const int rem  = dcap & 3;

    float ap0 = (lane == 0) ? 1.0f : 0.0f;   // linear alpha, u = lane
    float ap1 = 0.0f;                        // u = lane + 32
    int   E   = 0;                           // accumulated log2 exponent

    const float* pw = sP;
    int base = 0;
    for (int s = 0; s < S; s++) {
        float p00 = pw[          lane], p01 = pw[1 * U_ +  lane];
        float p02 = pw[2 * U_ +  lane], p03 = pw[3 * U_ +  lane];
        float p04 = pw[4 * U_ +  lane];
        float p10 = pw[     32 + lane], p11 = pw[1 * U_ + 32 + lane];
        float p12 = pw[2 * U_ + 32 + lane], p13 = pw[3 * U_ + 32 + lane];
        float p14 = pw[4 * U_ + 32 + lane];

        s_al[base + 6  + lane] = ap0;
        s_al[base + 38 + lane] = ap1;
        __syncwarp();
        float a0m1 = s_al[base + 5  + lane];
        float a0m2 = s_al[base + 4  + lane];
        float a0m3 = s_al[base + 3  + lane];
        float a0m4 = s_al[base + 2  + lane];
        float a1m1 = s_al[base + 37 + lane];
        float a1m2 = s_al[base + 36 + lane];
        float a1m3 = s_al[base + 35 + lane];
        float a1m4 = s_al[base + 34 + lane];
        base ^= 72;

        float t00 = fmaf(ap0,  p00, a0m1 * p01);
        float t01 = fmaf(a0m2, p02, a0m3 * p03);
        ap0 = t00 + fmaf(a0m4, p04, t01);

        float t10 = fmaf(ap1,  p10, a1m1 * p11);
        float t11 = fmaf(a1m2, p12, a1m3 * p13);
        ap1 = t10 + fmaf(a1m4, p14, t11);

        if ((s & 3) == 3) {   // renormalize every 4 macro steps -> max ~ [1,2)
            float mv = fmaxf(ap0, (lane < 18) ? ap1 : 0.0f);
            #pragma unroll
            for (int o = 16; o; o >>= 1)
                mv = fmaxf(mv, __shfl_xor_sync(0xffffffffu, mv, o));
            int e = (__float_as_int(mv) >> 23) & 255;
            float sc = __int_as_float((254 - e) << 23);   // 2^(127-e)
            ap0 *= sc; ap1 *= sc;
            E += e - 127;
        }
        pw += P4S;
    }

    // convert to log2 domain: log2(alpha) = lg2(ap) + E + sum_{s<S} c_s
    float Cs = 0.0f;
    for (int i = 0; i < S; i++) Cs += s_c[i];
    float corr = (float)E + Cs;
    float al0 = lg2f(ap0) + corr;    // ap==0 -> -inf, correct
    float al1 = lg2f(ap1) + corr;

    // remainder single steps (<= 3), log2 domain
    int D = 4 * S;
    for (int r = 0; r < rem; r++, D++) {
        float l0  = __shfl_up_sync(0xffffffffu, al0, 1);
        float a31 = __shfl_sync   (0xffffffffu, al0, 31);
        float l1  = __shfl_up_sync(0xffffffffu, al1, 1);
        if (lane == 0) { l0 = NEG_INF; l1 = a31; }

        int u = lane;
        int tb = D - u, te = D + 1 - u;
        float bl0 = (tb >= 0 && tb <= T_ - 2) ? sbl[u * T_ + tb] : NEG_INF;
        float em0 = (u >= 1 && te >= 0 && te < T_) ? sem[(u - 1) * T_ + te] : NEG_INF;
        float x0 = al0 + bl0, y0 = l0 + em0;
        float mm0 = fmaxf(x0, y0);
        al0 = mm0 + lg2f(ex2f(x0 - mm0) + ex2f(y0 - mm0));

        u = lane + 32;
        tb = D - u; te = D + 1 - u;
        float bl1 = (u < U_ && tb >= 0 && tb <= T_ - 2) ? sbl[u * T_ + tb] : NEG_INF;
        float em1 = (u < U_ && te >= 0 && te < T_) ? sem[(u - 1) * T_ + te] : NEG_INF;
        float x1 = al1 + bl1, y1 = l1 + em1;
        float mm1 = fmaxf(x1, y1);
        al1 = mm1 + lg2f(ex2f(x1 - mm1) + ex2f(y1 - mm1));
    }

    const bool own0 = (lane == ui);
    const bool own1 = (lane + 32 == ui);
    if (own0 | own1) {
        float a   = own0 ? al0 : al1;
        float fin = (a + sbl[ui * T_ + ti]) * LN2_F;
        g_partial[b] = fin;
        __threadfence();
        if (atomicAdd(&g_count, 1) == B_ - 1) {
            __threadfence();
            float sum = 0.0f;
            #pragma unroll
            for (int i = 0; i < B_; i++) sum += *((volatile float*)&g_partial[i]);
            out[0] = -sum * (1.0f / (float)B_);
            g_count = 0;   // reset for next graph replay
        }
    }
}

extern "C" void kernel_launch(void* const* d_in, const int* in_sizes, int n_in,
                              void* d_out, int out_size)
{
    (void)in_sizes; (void)n_in; (void)out_size;
    const float* h           = (const float*)d_in[0];
    const int*   targets     = (const int*)d_in[1];
    const int*   input_lens  = (const int*)d_in[2];
    const int*   target_lens = (const int*)d_in[3];

    cudaFuncSetAttribute(rnnt_phase2, cudaFuncAttributeMaxDynamicSharedMemorySize, SMEM_BYTES);

    rnnt_phase1<<<B_ * NC_, 256>>>(h, targets);
    rnnt_compose<<<B_ * NS_, 64>>>();
    rnnt_phase2<<<B_, 512, SMEM_BYTES>>>(input_lens, target_lens, (float*)d_out);
}